// round 1
// baseline (speedup 1.0000x reference)
#include <cuda_runtime.h>

// ---------------------------------------------------------------------------
// Packed f32x2 helpers (Blackwell FFMA2 path — 2x fp32 FMA throughput)
// ---------------------------------------------------------------------------
static __device__ __forceinline__ void ffma2(unsigned long long &d,
                                             unsigned long long a,
                                             unsigned long long b) {
    asm("fma.rn.f32x2 %0, %1, %2, %0;" : "+l"(d) : "l"(a), "l"(b));
}
static __device__ __forceinline__ unsigned long long splat2(float f) {
    unsigned long long r;
    asm("mov.b64 %0, {%1, %1};" : "=l"(r) : "f"(f));
    return r;
}
static __device__ __forceinline__ void unpack2(unsigned long long v, float &lo, float &hi) {
    asm("mov.b64 {%0, %1}, %2;" : "=f"(lo), "=f"(hi) : "l"(v));
}

// ---------------------------------------------------------------------------
// Static scratch pool (no cudaMalloc allowed). Carved at launch from in_sizes.
// 420M floats = 1.68 GB, ample for all intermediate feature maps.
// ---------------------------------------------------------------------------
#define POOL_FLOATS 420000000LL
__device__ float g_pool[POOL_FLOATS];

enum { M_BLOCK = 0, M_RES = 1, M_RED = 2 };

// Accumulate 4 input channels (one float4 of the gathered feature row)
// against W rows staged in shared memory. W reads are warp-uniform broadcasts.
template<int COUT>
static __device__ __forceinline__ void accum4(float4 f,
                                              const float* __restrict__ wrow,
                                              unsigned long long* acc) {
    const float fv[4] = {f.x, f.y, f.z, f.w};
#pragma unroll
    for (int u = 0; u < 4; u++) {
        unsigned long long fp = splat2(fv[u]);
        const ulonglong2* w2 = reinterpret_cast<const ulonglong2*>(wrow + u * COUT);
#pragma unroll
        for (int j = 0; j < COUT / 4; j++) {
            ulonglong2 wv = w2[j];
            ffma2(acc[2 * j + 0], fp, wv.x);
            ffma2(acc[2 * j + 1], fp, wv.y);
        }
    }
}

// ---------------------------------------------------------------------------
// Fused sparse gather-conv:
//   out[r] = epilogue( sum_{k=0..26, nbr[r][k]>=0} cat(featA,featB)[nbr[r][k]] @ W[k] )
// MODE = M_BLOCK: relu(conv*s + b)
// MODE = M_RES  : relu(conv*s + b + res[r])
// MODE = M_RED  : relu(conv*s + b) + pairsum(cat(featA,featB)[r])
// ---------------------------------------------------------------------------
template<int CINA, int CINB, int COUT, int MODE>
__global__ void __launch_bounds__(256, 2)
conv_kernel(const float* __restrict__ featA, const float* __restrict__ featB,
            const int* __restrict__ nbr, const float* __restrict__ W,
            const float* __restrict__ sb, const float* __restrict__ res,
            float* __restrict__ out, int N) {
    constexpr int CIN = CINA + CINB;
    __shared__ __align__(16) float Wk[CIN * COUT];

    const int tid = threadIdx.x;
    const int r = blockIdx.x * 256 + tid;
    const bool active = (r < N);

    unsigned long long acc[COUT / 2];
#pragma unroll
    for (int j = 0; j < COUT / 2; j++) acc[j] = 0ULL;

    const int* nb = nbr + (long long)r * 27;

    for (int k = 0; k < 27; k++) {
        __syncthreads();  // protect previous iteration's Wk reads
        {
            const float4* wg = reinterpret_cast<const float4*>(W + (long long)k * CIN * COUT);
            constexpr int NV = CIN * COUT / 4;
            for (int i = tid; i < NV; i += 256)
                reinterpret_cast<float4*>(Wk)[i] = wg[i];
        }
        __syncthreads();

        int idx = active ? nb[k] : -1;
        if (idx >= 0) {
            const float4* fa = reinterpret_cast<const float4*>(featA + (long long)idx * CINA);
            for (int c4 = 0; c4 < CINA / 4; c4++) {
                float4 f = fa[c4];
                accum4<COUT>(f, Wk + (c4 * 4) * COUT, acc);
            }
            if constexpr (CINB > 0) {
                const float4* fb = reinterpret_cast<const float4*>(featB + (long long)idx * CINB);
                for (int c4 = 0; c4 < CINB / 4; c4++) {
                    float4 f = fb[c4];
                    accum4<COUT>(f, Wk + (CINA + c4 * 4) * COUT, acc);
                }
            }
        }
    }

    if (!active) return;

    const float* scale = sb;
    const float* bias  = sb + COUT;
    float* o = out + (long long)r * COUT;
    const float* resr = (MODE == M_RES) ? (res + (long long)r * COUT) : nullptr;
    const float* cA = featA + (long long)r * CINA;  // for M_RED (cat row r)
    const float* cB = (CINB > 0) ? (featB + (long long)r * CINB) : nullptr;

#pragma unroll
    for (int j = 0; j < COUT / 2; j++) {
        float a0, a1;
        unpack2(acc[j], a0, a1);
        const int c0 = 2 * j, c1 = 2 * j + 1;
        float v0 = a0 * scale[c0] + bias[c0];
        float v1 = a1 * scale[c1] + bias[c1];
        if constexpr (MODE == M_RES) {
            v0 += resr[c0];
            v1 += resr[c1];
        }
        v0 = fmaxf(v0, 0.0f);
        v1 = fmaxf(v1, 0.0f);
        if constexpr (MODE == M_RED) {
            // reduce(cat)[c] = cat[2c] + cat[2c+1]; cat = [featA_row | featB_row]
#pragma unroll
            for (int t = 0; t < 2; t++) {
                const int c = (t == 0) ? c0 : c1;
                float rsum;
                if (2 * c + 1 < CINA) {
                    rsum = cA[2 * c] + cA[2 * c + 1];
                } else {
                    rsum = cB[2 * c - CINA] + cB[2 * c + 1 - CINA];
                }
                if (t == 0) v0 += rsum; else v1 += rsum;
            }
        }
        o[c0] = v0;
        o[c1] = v1;
    }
}

// ---------------------------------------------------------------------------
// Host orchestration
// ---------------------------------------------------------------------------
extern "C" void kernel_launch(void* const* d_in, const int* in_sizes, int n_in,
                              void* d_out, int out_size) {
    (void)n_in; (void)out_size;
    const float* vf     = (const float*)d_in[0];
    const float* Win    = (const float*)d_in[1];
    const float* W32    = (const float*)d_in[2];
    const float* W64    = (const float*)d_in[3];
    const float* Wd3    = (const float*)d_in[4];
    const float* W6432  = (const float*)d_in[5];
    const float* W12864 = (const float*)d_in[6];
    const float* bn32   = (const float*)d_in[7];
    const float* bn64   = (const float*)d_in[8];
    const int* nbr1  = (const int*)d_in[9];
    const int* nbr2  = (const int*)d_in[10];
    const int* nbr3  = (const int*)d_in[11];
    const int* nbr4  = (const int*)d_in[12];
    const int* nbrd2 = (const int*)d_in[13];
    const int* nbrd3 = (const int*)d_in[14];
    const int* nbrd4 = (const int*)d_in[15];
    const int* nbri4 = (const int*)d_in[16];
    const int* nbri3 = (const int*)d_in[17];
    const int* nbri2 = (const int*)d_in[18];

    const int N1 = in_sizes[9]  / 27;
    const int N2 = in_sizes[10] / 27;
    const int N3 = in_sizes[11] / 27;
    const int N4 = in_sizes[12] / 27;

    float* pool = nullptr;
    cudaGetSymbolAddress((void**)&pool, g_pool);
    size_t off = 0;
    auto alloc = [&](size_t nfloats) { float* p = pool + off; off += nfloats; return p; };

    // Level buffers (exact liveness; all 128B-aligned since N*32 floats)
    float* L1a = alloc((size_t)N1 * 32);
    float* L1b = alloc((size_t)N1 * 32);
    float* L1c = alloc((size_t)N1 * 32);
    float* L1d = alloc((size_t)N1 * 32);
    float* L1e = alloc((size_t)N1 * 32);
    float* L2a = alloc((size_t)N2 * 32);
    float* L2b = alloc((size_t)N2 * 32);
    float* L2c = alloc((size_t)N2 * 32);
    float* L2d = alloc((size_t)N2 * 32);
    float* L3a = alloc((size_t)N3 * 64);
    float* L3b = alloc((size_t)N3 * 64);
    float* L3c = alloc((size_t)N3 * 64);
    float* L3d = alloc((size_t)N3 * 64);
    float* L4a = alloc((size_t)N4 * 64);
    float* L4b = alloc((size_t)N4 * 64);
    float* L4c = alloc((size_t)N4 * 64);

    // Weight strides (floats)
    const long long W32S = 27LL * 32 * 32;      // 27648
    const long long W64S = 27LL * 64 * 64;      // 110592
    const long long W6432S = 27LL * 64 * 32;    // 55296
    const long long W12864S = 27LL * 128 * 64;  // 221184
    auto b32 = [&](int j) { return bn32 + (long long)j * 64; };
    auto b64 = [&](int j) { return bn64 + (long long)j * 128; };
    auto g = [](int n) { return dim3((unsigned)((n + 255) / 256)); };

    // ---- Encoder ----
    conv_kernel<4, 0, 32, M_BLOCK><<<g(N1), 256>>>(vf, nullptr, nbr1, Win, b32(0), nullptr, L1a, N1);
    conv_kernel<32, 0, 32, M_BLOCK><<<g(N1), 256>>>(L1a, nullptr, nbr1, W32 + 0 * W32S, b32(1), nullptr, L1b, N1);   // x1
    conv_kernel<32, 0, 32, M_BLOCK><<<g(N2), 256>>>(L1b, nullptr, nbrd2, W32 + 1 * W32S, b32(2), nullptr, L2a, N2);
    conv_kernel<32, 0, 32, M_BLOCK><<<g(N2), 256>>>(L2a, nullptr, nbr2, W32 + 2 * W32S, b32(3), nullptr, L2b, N2);
    conv_kernel<32, 0, 32, M_BLOCK><<<g(N2), 256>>>(L2b, nullptr, nbr2, W32 + 3 * W32S, b32(4), nullptr, L2a, N2);   // x2
    conv_kernel<32, 0, 64, M_BLOCK><<<g(N3), 256>>>(L2a, nullptr, nbrd3, Wd3, b64(0), nullptr, L3a, N3);
    conv_kernel<64, 0, 64, M_BLOCK><<<g(N3), 256>>>(L3a, nullptr, nbr3, W64 + 0 * W64S, b64(1), nullptr, L3b, N3);
    conv_kernel<64, 0, 64, M_BLOCK><<<g(N3), 256>>>(L3b, nullptr, nbr3, W64 + 1 * W64S, b64(2), nullptr, L3a, N3);   // x3
    conv_kernel<64, 0, 64, M_BLOCK><<<g(N4), 256>>>(L3a, nullptr, nbrd4, W64 + 2 * W64S, b64(3), nullptr, L4a, N4);
    conv_kernel<64, 0, 64, M_BLOCK><<<g(N4), 256>>>(L4a, nullptr, nbr4, W64 + 3 * W64S, b64(4), nullptr, L4b, N4);
    conv_kernel<64, 0, 64, M_BLOCK><<<g(N4), 256>>>(L4b, nullptr, nbr4, W64 + 4 * W64S, b64(5), nullptr, L4a, N4);   // x4

    // ---- Bottom: basic(x4) + concat conv + reduce ----
    conv_kernel<64, 0, 64, M_BLOCK><<<g(N4), 256>>>(L4a, nullptr, nbr4, W64 + 5 * W64S, b64(6), nullptr, L4b, N4);
    conv_kernel<64, 0, 64, M_RES><<<g(N4), 256>>>(L4b, nullptr, nbr4, W64 + 6 * W64S, b64(7), L4a, L4c, N4);         // t
    conv_kernel<64, 64, 64, M_RED><<<g(N4), 256>>>(L4a, L4c, nbr4, W12864 + 0 * W12864S, b64(11), nullptr, L4b, N4); // x

    // ---- Decoder level 3 ----
    conv_kernel<64, 0, 64, M_BLOCK><<<g(N3), 256>>>(L4b, nullptr, nbri4, W64 + 7 * W64S, b64(8), nullptr, L3b, N3);  // xu4
    conv_kernel<64, 0, 64, M_BLOCK><<<g(N3), 256>>>(L3a, nullptr, nbr3, W64 + 8 * W64S, b64(9), nullptr, L3c, N3);
    conv_kernel<64, 0, 64, M_RES><<<g(N3), 256>>>(L3c, nullptr, nbr3, W64 + 9 * W64S, b64(10), L3a, L3d, N3);        // t
    conv_kernel<64, 64, 64, M_RED><<<g(N3), 256>>>(L3b, L3d, nbr3, W12864 + 1 * W12864S, b64(12), nullptr, L3c, N3); // x

    // ---- Decoder level 2 ----
    conv_kernel<64, 0, 32, M_BLOCK><<<g(N2), 256>>>(L3c, nullptr, nbri3, W6432 + 0 * W6432S, b32(11), nullptr, L2b, N2); // xu3
    conv_kernel<32, 0, 32, M_BLOCK><<<g(N2), 256>>>(L2a, nullptr, nbr2, W32 + 4 * W32S, b32(5), nullptr, L2c, N2);
    conv_kernel<32, 0, 32, M_RES><<<g(N2), 256>>>(L2c, nullptr, nbr2, W32 + 5 * W32S, b32(6), L2a, L2d, N2);             // t
    conv_kernel<32, 32, 32, M_RED><<<g(N2), 256>>>(L2b, L2d, nbr2, W6432 + 1 * W6432S, b32(12), nullptr, L2c, N2);       // x

    // ---- Decoder level 1 ----
    conv_kernel<32, 0, 32, M_BLOCK><<<g(N1), 256>>>(L2c, nullptr, nbri2, W32 + 6 * W32S, b32(7), nullptr, L1c, N1);  // xu2
    conv_kernel<32, 0, 32, M_BLOCK><<<g(N1), 256>>>(L1b, nullptr, nbr1, W32 + 7 * W32S, b32(8), nullptr, L1d, N1);
    conv_kernel<32, 0, 32, M_RES><<<g(N1), 256>>>(L1d, nullptr, nbr1, W32 + 8 * W32S, b32(9), L1b, L1e, N1);         // t
    conv_kernel<32, 32, 32, M_RED><<<g(N1), 256>>>(L1c, L1e, nbr1, W6432 + 2 * W6432S, b32(13), nullptr, L1d, N1);   // x

    // ---- Output ----
    conv_kernel<32, 0, 32, M_BLOCK><<<g(N1), 256>>>(L1d, nullptr, nbr1, W32 + 9 * W32S, b32(10), nullptr,
                                                    (float*)d_out, N1);
}